// round 11
// baseline (speedup 1.0000x reference)
#include <cuda_runtime.h>
#include <math.h>

#define B    2
#define C    64
#define H    192
#define W    192
#define SH   384
#define SW   384
#define NPIX (H*W)     // 36864
#define NOUT (SH*SW)   // 147456

typedef unsigned long long ull;

// ---------------- device scratch ----------------
__device__ float2 d_feat2[C*NPIX];     // feat channel-major: [c][pix] -> (b0,b1)
__device__ float  d_wt[3*C*C];         // conv weights transposed: [g][c][o]
__device__ float2 d_wcmix[4*C*8];      // per-class mixed compress, dup-packed [cls][c][k]
__device__ float2 d_wemix[4*C*8];      // per-class mixed expand,   dup-packed [cls][c][k]
__device__ float  d_offs[8];           // per-class offsets

// ---------------- packed f32x2 helpers ----------------
__device__ __forceinline__ ull fma2(ull a, ull b, ull c){
    ull d; asm("fma.rn.f32x2 %0, %1, %2, %3;" : "=l"(d) : "l"(a), "l"(b), "l"(c)); return d;
}
__device__ __forceinline__ ull mul2(ull a, ull b){
    ull d; asm("mul.rn.f32x2 %0, %1, %2;" : "=l"(d) : "l"(a), "l"(b)); return d;
}
__device__ __forceinline__ ull pk2(float x, float y){
    ull u; asm("mov.b64 %0, {%1, %2};" : "=l"(u) : "f"(x), "f"(y)); return u;
}
__device__ __forceinline__ float2 upk(ull u){
    float2 v; asm("mov.b64 {%0, %1}, %2;" : "=f"(v.x), "=f"(v.y) : "l"(u)); return v;
}

// dummy kernel: keeps ncu capture index landing on a hot kernel
__global__ void align_kernel() {}

// ============================================================================
// Transpose kernel: coalesced read of wcv, scatter to d_wt[g][c][o].
// ============================================================================
__global__ void transpose_kernel(const float* __restrict__ wcv)
{
    int base = blockIdx.x * 1024;
    int tid = threadIdx.x;
    #pragma unroll
    for (int k = 0; k < 4; k++) {
        int idx = base + k*256 + tid;          // idx = o*192 + g*64 + c
        int o = idx / 192, r = idx - o*192;
        int g = r >> 6, c = r & 63;
        d_wt[g*4096 + c*64 + o] = wcv[idx];
    }
}

// ============================================================================
// Kernel A: 4-parity-class MLP + per-class mixed matrices (1 block, s2).
// ============================================================================
__global__ void param_kernel(const float* __restrict__ wce, const float* __restrict__ wee,
                             const float* __restrict__ w1,  const float* __restrict__ b1,
                             const float* __restrict__ w2,  const float* __restrict__ b2,
                             const float* __restrict__ wr,  const float* __restrict__ br,
                             const float* __restrict__ wo,  const float* __restrict__ bo,
                             const int* __restrict__ scale_p, const int* __restrict__ scale2_p)
{
    int tid = threadIdx.x;   // 256
    __shared__ float s_emb1[4][64];
    __shared__ float s_emb [4][64];
    __shared__ float s_rout[4][4];
    int cls = tid >> 6, o = tid & 63;
    float sc  = (float)(*scale_p);
    float sc2 = (float)(*scale2_p);

    int ip = cls >> 1, jp = cls & 1;
    float ihv = (ip + 0.5f) / sc;
    float ch  = ihv - floorf(ihv + 0.001f) - 0.5f;
    float iwv = (jp + 0.5f) / sc2;
    float cw  = iwv - floorf(iwv + 0.001f) - 0.5f;
    float i0 = 1.0f / sc2, i1 = 1.0f / sc;

    float4 w1v = __ldg((const float4*)(w1 + o*4));
    float z = w1v.x*i0 + w1v.y*i1 + w1v.z*ch + w1v.w*cw + b1[o];
    s_emb1[cls][o] = fmaxf(z, 0.0f);
    __syncthreads();

    float z2 = b2[o];
    const float4* w2v = (const float4*)(w2 + o*64);
    #pragma unroll
    for (int j4 = 0; j4 < 16; j4++) {
        float4 wv = __ldg(&w2v[j4]);
        z2 += wv.x*s_emb1[cls][j4*4+0] + wv.y*s_emb1[cls][j4*4+1]
            + wv.z*s_emb1[cls][j4*4+2] + wv.w*s_emb1[cls][j4*4+3];
    }
    s_emb[cls][o] = fmaxf(z2, 0.0f);
    __syncthreads();

    if (o < 4) {
        float zr = br[o];
        const float4* wrv = (const float4*)(wr + o*64);
        #pragma unroll
        for (int j4 = 0; j4 < 16; j4++) {
            float4 wv = __ldg(&wrv[j4]);
            zr += wv.x*s_emb[cls][j4*4+0] + wv.y*s_emb[cls][j4*4+1]
                + wv.z*s_emb[cls][j4*4+2] + wv.w*s_emb[cls][j4*4+3];
        }
        s_rout[cls][o] = 1.0f / (1.0f + expf(-zr));
    } else if (o < 6) {
        int d = o - 4;
        float zo = bo[d];
        const float4* wov = (const float4*)(wo + d*64);
        #pragma unroll
        for (int j4 = 0; j4 < 16; j4++) {
            float4 wv = __ldg(&wov[j4]);
            zo += wv.x*s_emb[cls][j4*4+0] + wv.y*s_emb[cls][j4*4+1]
                + wv.z*s_emb[cls][j4*4+2] + wv.w*s_emb[cls][j4*4+3];
        }
        d_offs[cls*2 + d] = zo;
    }
    __syncthreads();

    for (int idx = tid; idx < 4*512; idx += 256) {
        int cc = idx >> 9, r = idx & 511, c = r & 63, k = r >> 6;
        float r0 = s_rout[cc][0], r1 = s_rout[cc][1], r2 = s_rout[cc][2], r3 = s_rout[cc][3];
        float vc = r0*wce[0*512 + k*64 + c] + r1*wce[1*512 + k*64 + c]
                 + r2*wce[2*512 + k*64 + c] + r3*wce[3*512 + k*64 + c];
        d_wcmix[cc*512 + c*8 + k] = make_float2(vc, vc);
        float ve = r0*wee[0*512 + c*8 + k] + r1*wee[1*512 + c*8 + k]
                 + r2*wee[2*512 + c*8 + k] + r3*wee[3*512 + c*8 + k];
        d_wemix[cc*512 + c*8 + k] = make_float2(ve, ve);
    }
}

// ============================================================================
// Kernel B: fused Sobel + 1x1 conv (192->64), 16x8 tile, 128 threads,
// out-channel halves, 2 pixels/thread. yblk0 = band row-block offset.
// ============================================================================
__global__ __launch_bounds__(128) void feat_kernel(const float* __restrict__ x,
                                                   const float* __restrict__ bcv,
                                                   int yblk0)
{
    __shared__ float s_tile[16][180];
    __shared__ float s_w[16][192];
    int tid = threadIdx.x;
    int slot = tid & 63;
    int half = tid >> 6;
    int obase = half * 32;
    int r0 = slot >> 4;
    int cx = slot & 15;
    int bx = blockIdx.x * 16, by = (blockIdx.y + yblk0) * 8;
    int batch = blockIdx.z;
    const float* xb = x + batch * (C*NPIX);

    ull acc[32];
    #pragma unroll
    for (int i = 0; i < 32; i++) acc[i] = 0ULL;

    for (int ccb = 0; ccb < 64; ccb += 16) {
        __syncthreads();
        for (int e = tid; e < 16*180; e += 128) {
            int c8 = e / 180, p = e - c8*180;
            int py = p / 18, px = p - py*18;
            int gy = by + py - 1, gx = bx + px - 1;
            float v = 0.0f;
            if (gy >= 0 && gy < H && gx >= 0 && gx < W)
                v = xb[(ccb + c8)*NPIX + gy*W + gx];
            s_tile[c8][p] = v;
        }
        for (int e = tid; e < 16*192; e += 128) {
            int c8 = e / 192, r = e - c8*192;
            int g = r >> 6, oo = r & 63;
            s_w[c8][r] = d_wt[g*4096 + (ccb + c8)*64 + oo];
        }
        __syncthreads();

        #pragma unroll 1
        for (int c8 = 0; c8 < 16; c8++) {
            const float* t = &s_tile[c8][r0*18 + cx];
            float a00=t[0],  a01=t[1],  a02=t[2];
            float a10=t[18], a11=t[19], a12=t[20];
            float a20=t[36], a21=t[37], a22=t[38];
            const float* u = t + 72;
            float b00=u[0],  b01=u[1],  b02=u[2];
            float b10=u[18], b11=u[19], b12=u[20];
            float b20=u[36], b21=u[37], b22=u[38];

            float va  = a11;
            float gxa = (a02 - a00) + 2.0f*(a12 - a10) + (a22 - a20);
            float gya = (a20 - a00) + 2.0f*(a21 - a01) + (a22 - a02);
            float vb  = b11;
            float gxb = (b02 - b00) + 2.0f*(b12 - b10) + (b22 - b20);
            float gyb = (b20 - b00) + 2.0f*(b21 - b01) + (b22 - b02);

            ull VA = pk2(va, va),  GXA = pk2(gxa, gxa), GYA = pk2(gya, gya);
            ull VB = pk2(vb, vb),  GXB = pk2(gxb, gxb), GYB = pk2(gyb, gyb);

            const ulonglong2* w0p = (const ulonglong2*)&s_w[c8][  0 + obase];
            const ulonglong2* w1p = (const ulonglong2*)&s_w[c8][ 64 + obase];
            const ulonglong2* w2p = (const ulonglong2*)&s_w[c8][128 + obase];
            #pragma unroll
            for (int wg = 0; wg < 8; wg++) {
                ulonglong2 w0 = w0p[wg], w1 = w1p[wg], w2 = w2p[wg];
                acc[wg*2+0]    = fma2(w0.x, VA,  acc[wg*2+0]);
                acc[wg*2+1]    = fma2(w0.y, VA,  acc[wg*2+1]);
                acc[16+wg*2+0] = fma2(w0.x, VB,  acc[16+wg*2+0]);
                acc[16+wg*2+1] = fma2(w0.y, VB,  acc[16+wg*2+1]);
                acc[wg*2+0]    = fma2(w1.x, GXA, acc[wg*2+0]);
                acc[wg*2+1]    = fma2(w1.y, GXA, acc[wg*2+1]);
                acc[16+wg*2+0] = fma2(w1.x, GXB, acc[16+wg*2+0]);
                acc[16+wg*2+1] = fma2(w1.y, GXB, acc[16+wg*2+1]);
                acc[wg*2+0]    = fma2(w2.x, GYA, acc[wg*2+0]);
                acc[wg*2+1]    = fma2(w2.y, GYA, acc[wg*2+1]);
                acc[16+wg*2+0] = fma2(w2.x, GYB, acc[16+wg*2+0]);
                acc[16+wg*2+1] = fma2(w2.y, GYB, acc[16+wg*2+1]);
            }
        }
    }

    int pixA = (by + r0)*W + (bx + cx);
    int pixB = pixA + 4*W;
    float* fout = (float*)d_feat2;
    #pragma unroll
    for (int wg = 0; wg < 8; wg++) {
        #pragma unroll
        for (int hh = 0; hh < 2; hh++) {
            int o0 = obase + wg*4 + hh*2;
            float bi0 = __ldg(&bcv[o0]), bi1 = __ldg(&bcv[o0+1]);
            float2 ra = upk(acc[wg*2 + hh]);
            fout[( o0   *NPIX + pixA)*2 + batch] = ra.x + bi0;
            fout[((o0+1)*NPIX + pixA)*2 + batch] = ra.y + bi1;
            float2 rb = upk(acc[16 + wg*2 + hh]);
            fout[( o0   *NPIX + pixB)*2 + batch] = rb.x + bi0;
            fout[((o0+1)*NPIX + pixB)*2 + batch] = rb.y + bi1;
        }
    }
}

// ============================================================================
// Kernel C: bilinear sample + per-class compress/expand + residual.
// 32x4 tile, 256 threads; warp = (class, channel-half). yblk0 = band offset.
// ============================================================================
__global__ __launch_bounds__(256, 2) void up_kernel(float* __restrict__ out, int yblk0)
{
    extern __shared__ char smem_raw[];
    float2* s_wc  = (float2*)smem_raw;          // 16KB  (reused as s_mid after pass1)
    float2* s_we  = s_wc + 2048;                // 16KB
    ull*    s_fea = (ull*)(s_we + 2048);        // 64KB: [c][pslot]
    ull*    s_mid = (ull*)smem_raw;             // overlay
    __shared__ float s_o[8];

    int tid = threadIdx.x;
    for (int e = tid; e < 2048; e += 256) { s_wc[e] = d_wcmix[e]; s_we[e] = d_wemix[e]; }
    if (tid < 8) s_o[tid] = d_offs[tid];
    __syncthreads();

    int warp = tid >> 5, lane = tid & 31;
    int cls  = warp & 3;
    int half = warp >> 2;
    int pslot = cls*32 + lane;
    int i = (blockIdx.y + yblk0)*4 + ((lane >> 4) << 1) + (cls >> 1);
    int j = blockIdx.x*32 + ((lane & 15) << 1) + (cls & 1);
    float offx = s_o[cls*2+0], offy = s_o[cls*2+1];

    float gy = ((i + 0.5f)*0.5f - 0.5f)*(2.0f/(H-1)) - 1.0f + offy*(2.0f/(H-1));
    float iyf = ((gy + 1.0f)*H - 1.0f)*0.5f;
    float y0f = floorf(iyf);
    float fy = iyf - y0f;
    int y0 = (int)y0f;
    float wy0 = 1.0f - fy, wy1 = fy;
    bool vy0 = (y0   >= 0) && (y0   < H);
    bool vy1 = (y0+1 >= 0) && (y0+1 < H);
    int cy0 = min(max(y0,   0), H-1);
    int cy1 = min(max(y0+1, 0), H-1);

    float gx = ((j + 0.5f)*0.5f - 0.5f)*(2.0f/(W-1)) - 1.0f + offx*(2.0f/(W-1));
    float ixf = ((gx + 1.0f)*W - 1.0f)*0.5f;
    float x0f = floorf(ixf);
    float fx = ixf - x0f;
    int x0 = (int)x0f;
    float wx0 = 1.0f - fx, wx1 = fx;
    bool vx0 = (x0   >= 0) && (x0   < W);
    bool vx1 = (x0+1 >= 0) && (x0+1 < W);
    float w00 = (vx0 && vy0) ? wx0*wy0 : 0.0f;
    float w01 = (vx1 && vy0) ? wx1*wy0 : 0.0f;
    float w10 = (vx0 && vy1) ? wx0*wy1 : 0.0f;
    float w11 = (vx1 && vy1) ? wx1*wy1 : 0.0f;
    int cx0 = min(max(x0,   0), W-1), cx1 = min(max(x0+1, 0), W-1);
    ull W00 = pk2(w00,w00), W01 = pk2(w01,w01), W10 = pk2(w10,w10), W11 = pk2(w11,w11);

    const ull* fb  = (const ull*)d_feat2 + (size_t)half*32*NPIX;
    const ull* P00 = fb + cy0*W + cx0;
    const ull* P01 = fb + cy0*W + cx1;
    const ull* P10 = fb + cy1*W + cx0;
    const ull* P11 = fb + cy1*W + cx1;

    const ulonglong2* wcp = (const ulonglong2*)(s_wc + cls*512) + half*32*4;
    ull* fp = s_fea + (size_t)half*32*128 + pslot;
    ull midp[8] = {0,0,0,0,0,0,0,0};
    #pragma unroll 4
    for (int cc = 0; cc < 32; cc++) {
        ull v =  mul2(W00, P00[cc*NPIX]);
        v = fma2(W01, P01[cc*NPIX], v);
        v = fma2(W10, P10[cc*NPIX], v);
        v = fma2(W11, P11[cc*NPIX], v);
        fp[cc*128] = v;
        #pragma unroll
        for (int kk = 0; kk < 4; kk++) {
            ulonglong2 w = wcp[cc*4 + kk];
            midp[kk*2  ] = fma2(w.x, v, midp[kk*2  ]);
            midp[kk*2+1] = fma2(w.y, v, midp[kk*2+1]);
        }
    }

    __syncthreads();
    #pragma unroll
    for (int k = 0; k < 8; k++)
        s_mid[(half*8 + k)*128 + pslot] = midp[k];
    __syncthreads();
    ull mid[8];
    #pragma unroll
    for (int k = 0; k < 8; k++) {
        float2 a = upk(midp[k]);
        float2 b = upk(s_mid[((1-half)*8 + k)*128 + pslot]);
        mid[k] = pk2(a.x + b.x, a.y + b.y);
    }

    const ulonglong2* wep = (const ulonglong2*)(s_we + cls*512) + half*32*4;
    float* o0 = out +          i*SW + j;
    float* o1 = out + C*NOUT + i*SW + j;
    #pragma unroll 4
    for (int cc = 0; cc < 32; cc++) {
        ull v = fp[cc*128];
        #pragma unroll
        for (int kk = 0; kk < 4; kk++) {
            ulonglong2 w = wep[cc*4 + kk];
            v = fma2(w.x, mid[kk*2  ], v);
            v = fma2(w.y, mid[kk*2+1], v);
        }
        float2 rr = upk(v);
        int cg = half*32 + cc;
        __stwt(&o0[(size_t)cg*NOUT], rr.x);
        __stwt(&o1[(size_t)cg*NOUT], rr.y);
    }
}

// ============================================================================
extern "C" void kernel_launch(void* const* d_in, const int* in_sizes, int n_in,
                              void* d_out, int out_size)
{
    const float* x   = (const float*)d_in[0];
    const float* wce = (const float*)d_in[1];
    const float* wee = (const float*)d_in[2];
    const float* w1  = (const float*)d_in[3];
    const float* b1  = (const float*)d_in[4];
    const float* w2  = (const float*)d_in[5];
    const float* b2  = (const float*)d_in[6];
    const float* wr  = (const float*)d_in[7];
    const float* br  = (const float*)d_in[8];
    const float* wo  = (const float*)d_in[9];
    const float* bo  = (const float*)d_in[10];
    const float* wcv = (const float*)d_in[11];
    const float* bcv = (const float*)d_in[12];
    const int* scale_p  = (const int*)d_in[13];
    const int* scale2_p = (const int*)d_in[14];
    float* out = (float*)d_out;

    static cudaStream_t s2 = nullptr, s3 = nullptr;
    static cudaEvent_t evFork = nullptr, evParam = nullptr, evFeatA = nullptr, evUpA = nullptr;
    static int init_done = 0;
    if (!init_done) {
        cudaFuncSetAttribute(up_kernel, cudaFuncAttributeMaxDynamicSharedMemorySize, 98304);
        cudaStreamCreateWithFlags(&s2, cudaStreamNonBlocking);
        cudaStreamCreateWithFlags(&s3, cudaStreamNonBlocking);
        cudaEventCreateWithFlags(&evFork,  cudaEventDisableTiming);
        cudaEventCreateWithFlags(&evParam, cudaEventDisableTiming);
        cudaEventCreateWithFlags(&evFeatA, cudaEventDisableTiming);
        cudaEventCreateWithFlags(&evUpA,   cudaEventDisableTiming);
        init_done = 1;
    }

    align_kernel<<<1, 32>>>();   // profiling index alignment

    // fork param onto s2 (only up depends on it)
    cudaEventRecord(evFork, 0);
    cudaStreamWaitEvent(s2, evFork, 0);
    param_kernel<<<1, 256, 0, s2>>>(wce, wee, w1, b1, w2, b2, wr, br, wo, bo, scale_p, scale2_p);
    cudaEventRecord(evParam, s2);

    // stream 0: transpose + feat band A (row blocks [0,13) = rows 0..103)
    transpose_kernel<<<12, 256>>>(wcv);
    dim3 gbA(W/16, 13, B);
    feat_kernel<<<gbA, 128>>>(x, bcv, 0);
    cudaEventRecord(evFeatA, 0);

    // s3: up band A (out rows 0..191, needs feat rows <= ~103) — overlaps feat band B
    cudaStreamWaitEvent(s3, evFeatA, 0);
    cudaStreamWaitEvent(s3, evParam, 0);
    dim3 gcA(SW/32, 48);
    up_kernel<<<gcA, 256, 98304, s3>>>(out, 0);

    // stream 0: feat band B (row blocks [13,24) = rows 104..191), concurrent with upA
    dim3 gbB(W/16, 11, B);
    feat_kernel<<<gbB, 128>>>(x, bcv, 13);

    // stream 0: up band B (out rows 192..383) after feat B (+param)
    cudaStreamWaitEvent(0, evParam, 0);
    dim3 gcB(SW/32, 48);
    up_kernel<<<gcB, 256, 98304>>>(out, 48);

    // join upA back into stream 0
    cudaEventRecord(evUpA, s3);
    cudaStreamWaitEvent(0, evUpA, 0);
}

// round 12
// speedup vs baseline: 1.1924x; 1.1924x over previous
#include <cuda_runtime.h>
#include <math.h>

#define B    2
#define C    64
#define H    192
#define W    192
#define SH   384
#define SW   384
#define NPIX (H*W)     // 36864
#define NOUT (SH*SW)   // 147456

typedef unsigned long long ull;

// ---------------- device scratch ----------------
__device__ float2 d_feat2[C*NPIX];     // feat channel-major: [c][pix] -> (b0,b1)
__device__ float  d_wt[3*C*C];         // conv weights transposed: [g][c][o]
__device__ float2 d_wcmix[4*C*8];      // per-class mixed compress, dup-packed [cls][c][k]
__device__ float2 d_wemix[4*C*8];      // per-class mixed expand,   dup-packed [cls][c][k]
__device__ float  d_offs[8];           // per-class offsets

// ---------------- packed f32x2 helpers ----------------
__device__ __forceinline__ ull fma2(ull a, ull b, ull c){
    ull d; asm("fma.rn.f32x2 %0, %1, %2, %3;" : "=l"(d) : "l"(a), "l"(b), "l"(c)); return d;
}
__device__ __forceinline__ ull mul2(ull a, ull b){
    ull d; asm("mul.rn.f32x2 %0, %1, %2;" : "=l"(d) : "l"(a), "l"(b)); return d;
}
__device__ __forceinline__ ull pk2(float x, float y){
    ull u; asm("mov.b64 %0, {%1, %2};" : "=l"(u) : "f"(x), "f"(y)); return u;
}
__device__ __forceinline__ float2 upk(ull u){
    float2 v; asm("mov.b64 {%0, %1}, %2;" : "=f"(v.x), "=f"(v.y) : "l"(u)); return v;
}

// dummy kernel: keeps ncu capture index landing on a hot kernel
__global__ void align_kernel() {}

// ============================================================================
// Transpose kernel: coalesced read of wcv, scatter to d_wt[g][c][o].
// ============================================================================
__global__ void transpose_kernel(const float* __restrict__ wcv)
{
    int base = blockIdx.x * 1024;
    int tid = threadIdx.x;
    #pragma unroll
    for (int k = 0; k < 4; k++) {
        int idx = base + k*256 + tid;          // idx = o*192 + g*64 + c
        int o = idx / 192, r = idx - o*192;
        int g = r >> 6, c = r & 63;
        d_wt[g*4096 + c*64 + o] = wcv[idx];
    }
}

// ============================================================================
// Kernel A: 4-parity-class MLP + per-class mixed matrices (1 block, s2).
// ============================================================================
__global__ void param_kernel(const float* __restrict__ wce, const float* __restrict__ wee,
                             const float* __restrict__ w1,  const float* __restrict__ b1,
                             const float* __restrict__ w2,  const float* __restrict__ b2,
                             const float* __restrict__ wr,  const float* __restrict__ br,
                             const float* __restrict__ wo,  const float* __restrict__ bo,
                             const int* __restrict__ scale_p, const int* __restrict__ scale2_p)
{
    int tid = threadIdx.x;   // 256
    __shared__ float s_emb1[4][64];
    __shared__ float s_emb [4][64];
    __shared__ float s_rout[4][4];
    int cls = tid >> 6, o = tid & 63;
    float sc  = (float)(*scale_p);
    float sc2 = (float)(*scale2_p);

    int ip = cls >> 1, jp = cls & 1;
    float ihv = (ip + 0.5f) / sc;
    float ch  = ihv - floorf(ihv + 0.001f) - 0.5f;
    float iwv = (jp + 0.5f) / sc2;
    float cw  = iwv - floorf(iwv + 0.001f) - 0.5f;
    float i0 = 1.0f / sc2, i1 = 1.0f / sc;

    float4 w1v = __ldg((const float4*)(w1 + o*4));
    float z = w1v.x*i0 + w1v.y*i1 + w1v.z*ch + w1v.w*cw + b1[o];
    s_emb1[cls][o] = fmaxf(z, 0.0f);
    __syncthreads();

    float z2 = b2[o];
    const float4* w2v = (const float4*)(w2 + o*64);
    #pragma unroll
    for (int j4 = 0; j4 < 16; j4++) {
        float4 wv = __ldg(&w2v[j4]);
        z2 += wv.x*s_emb1[cls][j4*4+0] + wv.y*s_emb1[cls][j4*4+1]
            + wv.z*s_emb1[cls][j4*4+2] + wv.w*s_emb1[cls][j4*4+3];
    }
    s_emb[cls][o] = fmaxf(z2, 0.0f);
    __syncthreads();

    if (o < 4) {
        float zr = br[o];
        const float4* wrv = (const float4*)(wr + o*64);
        #pragma unroll
        for (int j4 = 0; j4 < 16; j4++) {
            float4 wv = __ldg(&wrv[j4]);
            zr += wv.x*s_emb[cls][j4*4+0] + wv.y*s_emb[cls][j4*4+1]
                + wv.z*s_emb[cls][j4*4+2] + wv.w*s_emb[cls][j4*4+3];
        }
        s_rout[cls][o] = 1.0f / (1.0f + expf(-zr));
    } else if (o < 6) {
        int d = o - 4;
        float zo = bo[d];
        const float4* wov = (const float4*)(wo + d*64);
        #pragma unroll
        for (int j4 = 0; j4 < 16; j4++) {
            float4 wv = __ldg(&wov[j4]);
            zo += wv.x*s_emb[cls][j4*4+0] + wv.y*s_emb[cls][j4*4+1]
                + wv.z*s_emb[cls][j4*4+2] + wv.w*s_emb[cls][j4*4+3];
        }
        d_offs[cls*2 + d] = zo;
    }
    __syncthreads();

    for (int idx = tid; idx < 4*512; idx += 256) {
        int cc = idx >> 9, r = idx & 511, c = r & 63, k = r >> 6;
        float r0 = s_rout[cc][0], r1 = s_rout[cc][1], r2 = s_rout[cc][2], r3 = s_rout[cc][3];
        float vc = r0*wce[0*512 + k*64 + c] + r1*wce[1*512 + k*64 + c]
                 + r2*wce[2*512 + k*64 + c] + r3*wce[3*512 + k*64 + c];
        d_wcmix[cc*512 + c*8 + k] = make_float2(vc, vc);
        float ve = r0*wee[0*512 + c*8 + k] + r1*wee[1*512 + c*8 + k]
                 + r2*wee[2*512 + c*8 + k] + r3*wee[3*512 + c*8 + k];
        d_wemix[cc*512 + c*8 + k] = make_float2(ve, ve);
    }
}

// ============================================================================
// Kernel B v3: fused Sobel + 1x1 conv (192->64), 16x8 tile, 256 threads,
// 1 pixel/thread x 32 out-channels (halves). acc = 16 ull -> ~3 blocks/SM.
// ============================================================================
__global__ __launch_bounds__(256) void feat_kernel(const float* __restrict__ x,
                                                   const float* __restrict__ bcv)
{
    __shared__ float s_tile[16][180];   // [c8][10 rows x 18 cols halo]
    __shared__ float s_w[16][192];      // [c8][g*64+o]
    int tid = threadIdx.x;
    int slot = tid & 127;               // pixel slot
    int half = tid >> 7;                // out-channel half
    int obase = half * 32;
    int r0 = slot >> 4;                 // 0..7
    int cx = slot & 15;
    int bx = blockIdx.x * 16, by = blockIdx.y * 8;
    int batch = blockIdx.z;
    const float* xb = x + batch * (C*NPIX);

    ull acc[16];
    #pragma unroll
    for (int i = 0; i < 16; i++) acc[i] = 0ULL;

    for (int ccb = 0; ccb < 64; ccb += 16) {
        __syncthreads();
        for (int e = tid; e < 16*180; e += 256) {
            int c8 = e / 180, p = e - c8*180;
            int py = p / 18, px = p - py*18;
            int gy = by + py - 1, gx = bx + px - 1;
            float v = 0.0f;
            if (gy >= 0 && gy < H && gx >= 0 && gx < W)
                v = xb[(ccb + c8)*NPIX + gy*W + gx];
            s_tile[c8][p] = v;
        }
        for (int e = tid; e < 16*192; e += 256) {
            int c8 = e / 192, r = e - c8*192;
            int g = r >> 6, oo = r & 63;
            s_w[c8][r] = d_wt[g*4096 + (ccb + c8)*64 + oo];
        }
        __syncthreads();

        #pragma unroll 2
        for (int c8 = 0; c8 < 16; c8++) {
            const float* t = &s_tile[c8][r0*18 + cx];
            float a00=t[0],  a01=t[1],  a02=t[2];
            float a10=t[18], a11=t[19], a12=t[20];
            float a20=t[36], a21=t[37], a22=t[38];

            float v   = a11;
            float sgx = (a02 - a00) + 2.0f*(a12 - a10) + (a22 - a20);
            float sgy = (a20 - a00) + 2.0f*(a21 - a01) + (a22 - a02);
            ull V  = pk2(v,   v);
            ull GX = pk2(sgx, sgx);
            ull GY = pk2(sgy, sgy);

            const ulonglong2* w0p = (const ulonglong2*)&s_w[c8][  0 + obase];
            const ulonglong2* w1p = (const ulonglong2*)&s_w[c8][ 64 + obase];
            const ulonglong2* w2p = (const ulonglong2*)&s_w[c8][128 + obase];
            #pragma unroll
            for (int wg = 0; wg < 8; wg++) {
                ulonglong2 w0 = w0p[wg], w1 = w1p[wg], w2 = w2p[wg];
                acc[wg*2+0] = fma2(w0.x, V,  acc[wg*2+0]);
                acc[wg*2+1] = fma2(w0.y, V,  acc[wg*2+1]);
                acc[wg*2+0] = fma2(w1.x, GX, acc[wg*2+0]);
                acc[wg*2+1] = fma2(w1.y, GX, acc[wg*2+1]);
                acc[wg*2+0] = fma2(w2.x, GY, acc[wg*2+0]);
                acc[wg*2+1] = fma2(w2.y, GY, acc[wg*2+1]);
            }
        }
    }

    int pix = (by + r0)*W + (bx + cx);
    float* fout = (float*)d_feat2;
    #pragma unroll
    for (int wg = 0; wg < 8; wg++) {
        #pragma unroll
        for (int hh = 0; hh < 2; hh++) {
            int o0 = obase + wg*4 + hh*2;
            float2 ra = upk(acc[wg*2 + hh]);
            fout[( o0   *NPIX + pix)*2 + batch] = ra.x + __ldg(&bcv[o0]);
            fout[((o0+1)*NPIX + pix)*2 + batch] = ra.y + __ldg(&bcv[o0+1]);
        }
    }
}

// ============================================================================
// Kernel C: bilinear sample + per-class compress/expand + residual.
// 32x4 tile, 256 threads; warp = (class, channel-half). (R10 version)
// ============================================================================
__global__ __launch_bounds__(256, 2) void up_kernel(float* __restrict__ out)
{
    extern __shared__ char smem_raw[];
    float2* s_wc  = (float2*)smem_raw;          // 16KB  (reused as s_mid after pass1)
    float2* s_we  = s_wc + 2048;                // 16KB
    ull*    s_fea = (ull*)(s_we + 2048);        // 64KB: [c][pslot]
    ull*    s_mid = (ull*)smem_raw;             // overlay
    __shared__ float s_o[8];

    int tid = threadIdx.x;
    for (int e = tid; e < 2048; e += 256) { s_wc[e] = d_wcmix[e]; s_we[e] = d_wemix[e]; }
    if (tid < 8) s_o[tid] = d_offs[tid];
    __syncthreads();

    int warp = tid >> 5, lane = tid & 31;
    int cls  = warp & 3;
    int half = warp >> 2;
    int pslot = cls*32 + lane;
    int i = blockIdx.y*4  + ((lane >> 4) << 1) + (cls >> 1);
    int j = blockIdx.x*32 + ((lane & 15) << 1) + (cls & 1);
    float offx = s_o[cls*2+0], offy = s_o[cls*2+1];

    float gy = ((i + 0.5f)*0.5f - 0.5f)*(2.0f/(H-1)) - 1.0f + offy*(2.0f/(H-1));
    float iyf = ((gy + 1.0f)*H - 1.0f)*0.5f;
    float y0f = floorf(iyf);
    float fy = iyf - y0f;
    int y0 = (int)y0f;
    float wy0 = 1.0f - fy, wy1 = fy;
    bool vy0 = (y0   >= 0) && (y0   < H);
    bool vy1 = (y0+1 >= 0) && (y0+1 < H);
    int cy0 = min(max(y0,   0), H-1);
    int cy1 = min(max(y0+1, 0), H-1);

    float gx = ((j + 0.5f)*0.5f - 0.5f)*(2.0f/(W-1)) - 1.0f + offx*(2.0f/(W-1));
    float ixf = ((gx + 1.0f)*W - 1.0f)*0.5f;
    float x0f = floorf(ixf);
    float fx = ixf - x0f;
    int x0 = (int)x0f;
    float wx0 = 1.0f - fx, wx1 = fx;
    bool vx0 = (x0   >= 0) && (x0   < W);
    bool vx1 = (x0+1 >= 0) && (x0+1 < W);
    float w00 = (vx0 && vy0) ? wx0*wy0 : 0.0f;
    float w01 = (vx1 && vy0) ? wx1*wy0 : 0.0f;
    float w10 = (vx0 && vy1) ? wx0*wy1 : 0.0f;
    float w11 = (vx1 && vy1) ? wx1*wy1 : 0.0f;
    int cx0 = min(max(x0,   0), W-1), cx1 = min(max(x0+1, 0), W-1);
    ull W00 = pk2(w00,w00), W01 = pk2(w01,w01), W10 = pk2(w10,w10), W11 = pk2(w11,w11);

    const ull* fb  = (const ull*)d_feat2 + (size_t)half*32*NPIX;
    const ull* P00 = fb + cy0*W + cx0;
    const ull* P01 = fb + cy0*W + cx1;
    const ull* P10 = fb + cy1*W + cx0;
    const ull* P11 = fb + cy1*W + cx1;

    const ulonglong2* wcp = (const ulonglong2*)(s_wc + cls*512) + half*32*4;
    ull* fp = s_fea + (size_t)half*32*128 + pslot;
    ull midp[8] = {0,0,0,0,0,0,0,0};
    #pragma unroll 4
    for (int cc = 0; cc < 32; cc++) {
        ull v =  mul2(W00, P00[cc*NPIX]);
        v = fma2(W01, P01[cc*NPIX], v);
        v = fma2(W10, P10[cc*NPIX], v);
        v = fma2(W11, P11[cc*NPIX], v);
        fp[cc*128] = v;
        #pragma unroll
        for (int kk = 0; kk < 4; kk++) {
            ulonglong2 w = wcp[cc*4 + kk];
            midp[kk*2  ] = fma2(w.x, v, midp[kk*2  ]);
            midp[kk*2+1] = fma2(w.y, v, midp[kk*2+1]);
        }
    }

    __syncthreads();
    #pragma unroll
    for (int k = 0; k < 8; k++)
        s_mid[(half*8 + k)*128 + pslot] = midp[k];
    __syncthreads();
    ull mid[8];
    #pragma unroll
    for (int k = 0; k < 8; k++) {
        float2 a = upk(midp[k]);
        float2 b = upk(s_mid[((1-half)*8 + k)*128 + pslot]);
        mid[k] = pk2(a.x + b.x, a.y + b.y);
    }

    const ulonglong2* wep = (const ulonglong2*)(s_we + cls*512) + half*32*4;
    float* o0 = out +          i*SW + j;
    float* o1 = out + C*NOUT + i*SW + j;
    #pragma unroll 4
    for (int cc = 0; cc < 32; cc++) {
        ull v = fp[cc*128];
        #pragma unroll
        for (int kk = 0; kk < 4; kk++) {
            ulonglong2 w = wep[cc*4 + kk];
            v = fma2(w.x, mid[kk*2  ], v);
            v = fma2(w.y, mid[kk*2+1], v);
        }
        float2 rr = upk(v);
        int cg = half*32 + cc;
        __stwt(&o0[(size_t)cg*NOUT], rr.x);
        __stwt(&o1[(size_t)cg*NOUT], rr.y);
    }
}

// ============================================================================
extern "C" void kernel_launch(void* const* d_in, const int* in_sizes, int n_in,
                              void* d_out, int out_size)
{
    const float* x   = (const float*)d_in[0];
    const float* wce = (const float*)d_in[1];
    const float* wee = (const float*)d_in[2];
    const float* w1  = (const float*)d_in[3];
    const float* b1  = (const float*)d_in[4];
    const float* w2  = (const float*)d_in[5];
    const float* b2  = (const float*)d_in[6];
    const float* wr  = (const float*)d_in[7];
    const float* br  = (const float*)d_in[8];
    const float* wo  = (const float*)d_in[9];
    const float* bo  = (const float*)d_in[10];
    const float* wcv = (const float*)d_in[11];
    const float* bcv = (const float*)d_in[12];
    const int* scale_p  = (const int*)d_in[13];
    const int* scale2_p = (const int*)d_in[14];
    float* out = (float*)d_out;

    static cudaStream_t s2 = nullptr;
    static cudaEvent_t evFork = nullptr, evParam = nullptr;
    static int init_done = 0;
    if (!init_done) {
        cudaFuncSetAttribute(up_kernel, cudaFuncAttributeMaxDynamicSharedMemorySize, 98304);
        cudaStreamCreateWithFlags(&s2, cudaStreamNonBlocking);
        cudaEventCreateWithFlags(&evFork,  cudaEventDisableTiming);
        cudaEventCreateWithFlags(&evParam, cudaEventDisableTiming);
        init_done = 1;
    }

    align_kernel<<<1, 32>>>();   // profiling index alignment

    // fork param onto s2 (only up depends on it)
    cudaEventRecord(evFork, 0);
    cudaStreamWaitEvent(s2, evFork, 0);
    param_kernel<<<1, 256, 0, s2>>>(wce, wee, w1, b1, w2, b2, wr, br, wo, bo, scale_p, scale2_p);
    cudaEventRecord(evParam, s2);

    // stream 0: transpose + feat
    transpose_kernel<<<12, 256>>>(wcv);
    dim3 gb(W/16, H/8, B);
    feat_kernel<<<gb, 256>>>(x, bcv);

    // join param, then up
    cudaStreamWaitEvent(0, evParam, 0);
    dim3 gc(SW/32, SH/4);
    up_kernel<<<gc, 256, 98304>>>(out);
}

// round 13
// speedup vs baseline: 1.3952x; 1.1701x over previous
#include <cuda_runtime.h>
#include <math.h>

#define B    2
#define C    64
#define H    192
#define W    192
#define SH   384
#define SW   384
#define NPIX (H*W)     // 36864
#define NOUT (SH*SW)   // 147456

typedef unsigned long long ull;

// ---------------- device scratch ----------------
__device__ float2 d_feat2[C*NPIX];     // feat channel-major: [c][pix] -> (b0,b1)
__device__ float  d_wt[3*C*C];         // conv weights transposed: [g][c][o]
__device__ float2 d_wcmix[4*C*8];      // per-class mixed compress, dup-packed [cls][c][k]
__device__ float2 d_wemix[4*C*8];      // per-class mixed expand,   dup-packed [cls][c][k]
__device__ float  d_offs[8];           // per-class offsets

// ---------------- packed f32x2 helpers ----------------
__device__ __forceinline__ ull fma2(ull a, ull b, ull c){
    ull d; asm("fma.rn.f32x2 %0, %1, %2, %3;" : "=l"(d) : "l"(a), "l"(b), "l"(c)); return d;
}
__device__ __forceinline__ ull mul2(ull a, ull b){
    ull d; asm("mul.rn.f32x2 %0, %1, %2;" : "=l"(d) : "l"(a), "l"(b)); return d;
}
__device__ __forceinline__ ull pk2(float x, float y){
    ull u; asm("mov.b64 %0, {%1, %2};" : "=l"(u) : "f"(x), "f"(y)); return u;
}
__device__ __forceinline__ float2 upk(ull u){
    float2 v; asm("mov.b64 {%0, %1}, %2;" : "=f"(v.x), "=f"(v.y) : "l"(u)); return v;
}

// dummy kernel: keeps ncu capture index landing on a hot kernel
__global__ void align_kernel() {}

// ============================================================================
// Transpose kernel: coalesced read of wcv, scatter to d_wt[g][c][o].
// ============================================================================
__global__ void transpose_kernel(const float* __restrict__ wcv)
{
    int base = blockIdx.x * 1024;
    int tid = threadIdx.x;
    #pragma unroll
    for (int k = 0; k < 4; k++) {
        int idx = base + k*256 + tid;          // idx = o*192 + g*64 + c
        int o = idx / 192, r = idx - o*192;
        int g = r >> 6, c = r & 63;
        d_wt[g*4096 + c*64 + o] = wcv[idx];
    }
}

// ============================================================================
// Kernel A: 4-parity-class MLP + per-class mixed matrices (1 block, s2).
// ============================================================================
__global__ void param_kernel(const float* __restrict__ wce, const float* __restrict__ wee,
                             const float* __restrict__ w1,  const float* __restrict__ b1,
                             const float* __restrict__ w2,  const float* __restrict__ b2,
                             const float* __restrict__ wr,  const float* __restrict__ br,
                             const float* __restrict__ wo,  const float* __restrict__ bo,
                             const int* __restrict__ scale_p, const int* __restrict__ scale2_p)
{
    int tid = threadIdx.x;   // 256
    __shared__ float s_emb1[4][64];
    __shared__ float s_emb [4][64];
    __shared__ float s_rout[4][4];
    int cls = tid >> 6, o = tid & 63;
    float sc  = (float)(*scale_p);
    float sc2 = (float)(*scale2_p);

    int ip = cls >> 1, jp = cls & 1;
    float ihv = (ip + 0.5f) / sc;
    float ch  = ihv - floorf(ihv + 0.001f) - 0.5f;
    float iwv = (jp + 0.5f) / sc2;
    float cw  = iwv - floorf(iwv + 0.001f) - 0.5f;
    float i0 = 1.0f / sc2, i1 = 1.0f / sc;

    float4 w1v = __ldg((const float4*)(w1 + o*4));
    float z = w1v.x*i0 + w1v.y*i1 + w1v.z*ch + w1v.w*cw + b1[o];
    s_emb1[cls][o] = fmaxf(z, 0.0f);
    __syncthreads();

    float z2 = b2[o];
    const float4* w2v = (const float4*)(w2 + o*64);
    #pragma unroll
    for (int j4 = 0; j4 < 16; j4++) {
        float4 wv = __ldg(&w2v[j4]);
        z2 += wv.x*s_emb1[cls][j4*4+0] + wv.y*s_emb1[cls][j4*4+1]
            + wv.z*s_emb1[cls][j4*4+2] + wv.w*s_emb1[cls][j4*4+3];
    }
    s_emb[cls][o] = fmaxf(z2, 0.0f);
    __syncthreads();

    if (o < 4) {
        float zr = br[o];
        const float4* wrv = (const float4*)(wr + o*64);
        #pragma unroll
        for (int j4 = 0; j4 < 16; j4++) {
            float4 wv = __ldg(&wrv[j4]);
            zr += wv.x*s_emb[cls][j4*4+0] + wv.y*s_emb[cls][j4*4+1]
                + wv.z*s_emb[cls][j4*4+2] + wv.w*s_emb[cls][j4*4+3];
        }
        s_rout[cls][o] = 1.0f / (1.0f + expf(-zr));
    } else if (o < 6) {
        int d = o - 4;
        float zo = bo[d];
        const float4* wov = (const float4*)(wo + d*64);
        #pragma unroll
        for (int j4 = 0; j4 < 16; j4++) {
            float4 wv = __ldg(&wov[j4]);
            zo += wv.x*s_emb[cls][j4*4+0] + wv.y*s_emb[cls][j4*4+1]
                + wv.z*s_emb[cls][j4*4+2] + wv.w*s_emb[cls][j4*4+3];
        }
        d_offs[cls*2 + d] = zo;
    }
    __syncthreads();

    for (int idx = tid; idx < 4*512; idx += 256) {
        int cc = idx >> 9, r = idx & 511, c = r & 63, k = r >> 6;
        float r0 = s_rout[cc][0], r1 = s_rout[cc][1], r2 = s_rout[cc][2], r3 = s_rout[cc][3];
        float vc = r0*wce[0*512 + k*64 + c] + r1*wce[1*512 + k*64 + c]
                 + r2*wce[2*512 + k*64 + c] + r3*wce[3*512 + k*64 + c];
        d_wcmix[cc*512 + c*8 + k] = make_float2(vc, vc);
        float ve = r0*wee[0*512 + c*8 + k] + r1*wee[1*512 + c*8 + k]
                 + r2*wee[2*512 + c*8 + k] + r3*wee[3*512 + c*8 + k];
        d_wemix[cc*512 + c*8 + k] = make_float2(ve, ve);
    }
}

// ============================================================================
// Kernel B: fused Sobel + 1x1 conv (192->64), 16x8 tile, 128 threads,
// out-channel halves, 2 pixels/thread (R10 config), c8 loop unroll 2.
// ============================================================================
__global__ __launch_bounds__(128) void feat_kernel(const float* __restrict__ x,
                                                   const float* __restrict__ bcv)
{
    __shared__ float s_tile[16][180];
    __shared__ float s_w[16][192];
    int tid = threadIdx.x;
    int slot = tid & 63;
    int half = tid >> 6;
    int obase = half * 32;
    int r0 = slot >> 4;
    int cx = slot & 15;
    int bx = blockIdx.x * 16, by = blockIdx.y * 8;
    int batch = blockIdx.z;
    const float* xb = x + batch * (C*NPIX);

    ull acc[32];
    #pragma unroll
    for (int i = 0; i < 32; i++) acc[i] = 0ULL;

    for (int ccb = 0; ccb < 64; ccb += 16) {
        __syncthreads();
        for (int e = tid; e < 16*180; e += 128) {
            int c8 = e / 180, p = e - c8*180;
            int py = p / 18, px = p - py*18;
            int gy = by + py - 1, gx = bx + px - 1;
            float v = 0.0f;
            if (gy >= 0 && gy < H && gx >= 0 && gx < W)
                v = xb[(ccb + c8)*NPIX + gy*W + gx];
            s_tile[c8][p] = v;
        }
        for (int e = tid; e < 16*192; e += 128) {
            int c8 = e / 192, r = e - c8*192;
            int g = r >> 6, oo = r & 63;
            s_w[c8][r] = d_wt[g*4096 + (ccb + c8)*64 + oo];
        }
        __syncthreads();

        #pragma unroll 2
        for (int c8 = 0; c8 < 16; c8++) {
            const float* t = &s_tile[c8][r0*18 + cx];
            float a00=t[0],  a01=t[1],  a02=t[2];
            float a10=t[18], a11=t[19], a12=t[20];
            float a20=t[36], a21=t[37], a22=t[38];
            const float* u = t + 72;
            float b00=u[0],  b01=u[1],  b02=u[2];
            float b10=u[18], b11=u[19], b12=u[20];
            float b20=u[36], b21=u[37], b22=u[38];

            float va  = a11;
            float gxa = (a02 - a00) + 2.0f*(a12 - a10) + (a22 - a20);
            float gya = (a20 - a00) + 2.0f*(a21 - a01) + (a22 - a02);
            float vb  = b11;
            float gxb = (b02 - b00) + 2.0f*(b12 - b10) + (b22 - b20);
            float gyb = (b20 - b00) + 2.0f*(b21 - b01) + (b22 - b02);

            ull VA = pk2(va, va),  GXA = pk2(gxa, gxa), GYA = pk2(gya, gya);
            ull VB = pk2(vb, vb),  GXB = pk2(gxb, gxb), GYB = pk2(gyb, gyb);

            const ulonglong2* w0p = (const ulonglong2*)&s_w[c8][  0 + obase];
            const ulonglong2* w1p = (const ulonglong2*)&s_w[c8][ 64 + obase];
            const ulonglong2* w2p = (const ulonglong2*)&s_w[c8][128 + obase];
            #pragma unroll
            for (int wg = 0; wg < 8; wg++) {
                ulonglong2 w0 = w0p[wg], w1 = w1p[wg], w2 = w2p[wg];
                acc[wg*2+0]    = fma2(w0.x, VA,  acc[wg*2+0]);
                acc[wg*2+1]    = fma2(w0.y, VA,  acc[wg*2+1]);
                acc[16+wg*2+0] = fma2(w0.x, VB,  acc[16+wg*2+0]);
                acc[16+wg*2+1] = fma2(w0.y, VB,  acc[16+wg*2+1]);
                acc[wg*2+0]    = fma2(w1.x, GXA, acc[wg*2+0]);
                acc[wg*2+1]    = fma2(w1.y, GXA, acc[wg*2+1]);
                acc[16+wg*2+0] = fma2(w1.x, GXB, acc[16+wg*2+0]);
                acc[16+wg*2+1] = fma2(w1.y, GXB, acc[16+wg*2+1]);
                acc[wg*2+0]    = fma2(w2.x, GYA, acc[wg*2+0]);
                acc[wg*2+1]    = fma2(w2.y, GYA, acc[wg*2+1]);
                acc[16+wg*2+0] = fma2(w2.x, GYB, acc[16+wg*2+0]);
                acc[16+wg*2+1] = fma2(w2.y, GYB, acc[16+wg*2+1]);
            }
        }
    }

    int pixA = (by + r0)*W + (bx + cx);
    int pixB = pixA + 4*W;
    float* fout = (float*)d_feat2;
    #pragma unroll
    for (int wg = 0; wg < 8; wg++) {
        #pragma unroll
        for (int hh = 0; hh < 2; hh++) {
            int o0 = obase + wg*4 + hh*2;
            float bi0 = __ldg(&bcv[o0]), bi1 = __ldg(&bcv[o0+1]);
            float2 ra = upk(acc[wg*2 + hh]);
            fout[( o0   *NPIX + pixA)*2 + batch] = ra.x + bi0;
            fout[((o0+1)*NPIX + pixA)*2 + batch] = ra.y + bi1;
            float2 rb = upk(acc[16 + wg*2 + hh]);
            fout[( o0   *NPIX + pixB)*2 + batch] = rb.x + bi0;
            fout[((o0+1)*NPIX + pixB)*2 + batch] = rb.y + bi1;
        }
    }
}

// ============================================================================
// Kernel C: bilinear sample + per-class compress/expand + residual.
// 32x4 tile, 256 threads; warp = (class, channel-half). (R10 version, untouched)
// ============================================================================
__global__ __launch_bounds__(256, 2) void up_kernel(float* __restrict__ out)
{
    extern __shared__ char smem_raw[];
    float2* s_wc  = (float2*)smem_raw;          // 16KB  (reused as s_mid after pass1)
    float2* s_we  = s_wc + 2048;                // 16KB
    ull*    s_fea = (ull*)(s_we + 2048);        // 64KB: [c][pslot]
    ull*    s_mid = (ull*)smem_raw;             // overlay
    __shared__ float s_o[8];

    int tid = threadIdx.x;
    for (int e = tid; e < 2048; e += 256) { s_wc[e] = d_wcmix[e]; s_we[e] = d_wemix[e]; }
    if (tid < 8) s_o[tid] = d_offs[tid];
    __syncthreads();

    int warp = tid >> 5, lane = tid & 31;
    int cls  = warp & 3;
    int half = warp >> 2;
    int pslot = cls*32 + lane;
    int i = blockIdx.y*4  + ((lane >> 4) << 1) + (cls >> 1);
    int j = blockIdx.x*32 + ((lane & 15) << 1) + (cls & 1);
    float offx = s_o[cls*2+0], offy = s_o[cls*2+1];

    float gy = ((i + 0.5f)*0.5f - 0.5f)*(2.0f/(H-1)) - 1.0f + offy*(2.0f/(H-1));
    float iyf = ((gy + 1.0f)*H - 1.0f)*0.5f;
    float y0f = floorf(iyf);
    float fy = iyf - y0f;
    int y0 = (int)y0f;
    float wy0 = 1.0f - fy, wy1 = fy;
    bool vy0 = (y0   >= 0) && (y0   < H);
    bool vy1 = (y0+1 >= 0) && (y0+1 < H);
    int cy0 = min(max(y0,   0), H-1);
    int cy1 = min(max(y0+1, 0), H-1);

    float gx = ((j + 0.5f)*0.5f - 0.5f)*(2.0f/(W-1)) - 1.0f + offx*(2.0f/(W-1));
    float ixf = ((gx + 1.0f)*W - 1.0f)*0.5f;
    float x0f = floorf(ixf);
    float fx = ixf - x0f;
    int x0 = (int)x0f;
    float wx0 = 1.0f - fx, wx1 = fx;
    bool vx0 = (x0   >= 0) && (x0   < W);
    bool vx1 = (x0+1 >= 0) && (x0+1 < W);
    float w00 = (vx0 && vy0) ? wx0*wy0 : 0.0f;
    float w01 = (vx1 && vy0) ? wx1*wy0 : 0.0f;
    float w10 = (vx0 && vy1) ? wx0*wy1 : 0.0f;
    float w11 = (vx1 && vy1) ? wx1*wy1 : 0.0f;
    int cx0 = min(max(x0,   0), W-1), cx1 = min(max(x0+1, 0), W-1);
    ull W00 = pk2(w00,w00), W01 = pk2(w01,w01), W10 = pk2(w10,w10), W11 = pk2(w11,w11);

    const ull* fb  = (const ull*)d_feat2 + (size_t)half*32*NPIX;
    const ull* P00 = fb + cy0*W + cx0;
    const ull* P01 = fb + cy0*W + cx1;
    const ull* P10 = fb + cy1*W + cx0;
    const ull* P11 = fb + cy1*W + cx1;

    const ulonglong2* wcp = (const ulonglong2*)(s_wc + cls*512) + half*32*4;
    ull* fp = s_fea + (size_t)half*32*128 + pslot;
    ull midp[8] = {0,0,0,0,0,0,0,0};
    #pragma unroll 4
    for (int cc = 0; cc < 32; cc++) {
        ull v =  mul2(W00, P00[cc*NPIX]);
        v = fma2(W01, P01[cc*NPIX], v);
        v = fma2(W10, P10[cc*NPIX], v);
        v = fma2(W11, P11[cc*NPIX], v);
        fp[cc*128] = v;
        #pragma unroll
        for (int kk = 0; kk < 4; kk++) {
            ulonglong2 w = wcp[cc*4 + kk];
            midp[kk*2  ] = fma2(w.x, v, midp[kk*2  ]);
            midp[kk*2+1] = fma2(w.y, v, midp[kk*2+1]);
        }
    }

    __syncthreads();
    #pragma unroll
    for (int k = 0; k < 8; k++)
        s_mid[(half*8 + k)*128 + pslot] = midp[k];
    __syncthreads();
    ull mid[8];
    #pragma unroll
    for (int k = 0; k < 8; k++) {
        float2 a = upk(midp[k]);
        float2 b = upk(s_mid[((1-half)*8 + k)*128 + pslot]);
        mid[k] = pk2(a.x + b.x, a.y + b.y);
    }

    const ulonglong2* wep = (const ulonglong2*)(s_we + cls*512) + half*32*4;
    float* o0 = out +          i*SW + j;
    float* o1 = out + C*NOUT + i*SW + j;
    #pragma unroll 4
    for (int cc = 0; cc < 32; cc++) {
        ull v = fp[cc*128];
        #pragma unroll
        for (int kk = 0; kk < 4; kk++) {
            ulonglong2 w = wep[cc*4 + kk];
            v = fma2(w.x, mid[kk*2  ], v);
            v = fma2(w.y, mid[kk*2+1], v);
        }
        float2 rr = upk(v);
        int cg = half*32 + cc;
        __stwt(&o0[(size_t)cg*NOUT], rr.x);
        __stwt(&o1[(size_t)cg*NOUT], rr.y);
    }
}

// ============================================================================
extern "C" void kernel_launch(void* const* d_in, const int* in_sizes, int n_in,
                              void* d_out, int out_size)
{
    const float* x   = (const float*)d_in[0];
    const float* wce = (const float*)d_in[1];
    const float* wee = (const float*)d_in[2];
    const float* w1  = (const float*)d_in[3];
    const float* b1  = (const float*)d_in[4];
    const float* w2  = (const float*)d_in[5];
    const float* b2  = (const float*)d_in[6];
    const float* wr  = (const float*)d_in[7];
    const float* br  = (const float*)d_in[8];
    const float* wo  = (const float*)d_in[9];
    const float* bo  = (const float*)d_in[10];
    const float* wcv = (const float*)d_in[11];
    const float* bcv = (const float*)d_in[12];
    const int* scale_p  = (const int*)d_in[13];
    const int* scale2_p = (const int*)d_in[14];
    float* out = (float*)d_out;

    static cudaStream_t s2 = nullptr;
    static cudaEvent_t evFork = nullptr, evParam = nullptr;
    static int init_done = 0;
    if (!init_done) {
        cudaFuncSetAttribute(up_kernel, cudaFuncAttributeMaxDynamicSharedMemorySize, 98304);
        cudaStreamCreateWithFlags(&s2, cudaStreamNonBlocking);
        cudaEventCreateWithFlags(&evFork,  cudaEventDisableTiming);
        cudaEventCreateWithFlags(&evParam, cudaEventDisableTiming);
        init_done = 1;
    }

    align_kernel<<<1, 32>>>();   // profiling index alignment

    // fork param onto s2 (only up depends on it)
    cudaEventRecord(evFork, 0);
    cudaStreamWaitEvent(s2, evFork, 0);
    param_kernel<<<1, 256, 0, s2>>>(wce, wee, w1, b1, w2, b2, wr, br, wo, bo, scale_p, scale2_p);
    cudaEventRecord(evParam, s2);

    // stream 0: transpose + feat
    transpose_kernel<<<12, 256>>>(wcv);
    dim3 gb(W/16, H/8, B);
    feat_kernel<<<gb, 128>>>(x, bcv);

    // join param, then up
    cudaStreamWaitEvent(0, evParam, 0);
    dim3 gc(SW/32, SH/4);
    up_kernel<<<gc, 256, 98304>>>(out);
}

// round 15
// speedup vs baseline: 1.4551x; 1.0430x over previous
#include <cuda_runtime.h>
#include <stdint.h>
#include <math.h>

#define B    2
#define C    64
#define H    192
#define W    192
#define SH   384
#define SW   384
#define NPIX (H*W)     // 36864
#define NOUT (SH*SW)   // 147456

typedef unsigned long long ull;

// ---------------- device scratch ----------------
__device__ float2 d_feat2[C*NPIX];     // feat channel-major: [c][pix] -> (b0,b1)
__device__ float  d_wt[3*C*C];         // conv weights transposed: [g][c][o]
__device__ float2 d_wcmix[4*C*8];      // per-class mixed compress, dup-packed [cls][c][k]
__device__ float2 d_wemix[4*C*8];      // per-class mixed expand,   dup-packed [cls][c][k]
__device__ float  d_offs[8];           // per-class offsets

// ---------------- packed f32x2 helpers ----------------
__device__ __forceinline__ ull fma2(ull a, ull b, ull c){
    ull d; asm("fma.rn.f32x2 %0, %1, %2, %3;" : "=l"(d) : "l"(a), "l"(b), "l"(c)); return d;
}
__device__ __forceinline__ ull mul2(ull a, ull b){
    ull d; asm("mul.rn.f32x2 %0, %1, %2;" : "=l"(d) : "l"(a), "l"(b)); return d;
}
__device__ __forceinline__ ull pk2(float x, float y){
    ull u; asm("mov.b64 %0, {%1, %2};" : "=l"(u) : "f"(x), "f"(y)); return u;
}
__device__ __forceinline__ float2 upk(ull u){
    float2 v; asm("mov.b64 {%0, %1}, %2;" : "=f"(v.x), "=f"(v.y) : "l"(u)); return v;
}
__device__ __forceinline__ unsigned int smem_u32(const void* p){
    unsigned int a;
    asm("{ .reg .u64 t; cvta.to.shared.u64 t, %1; cvt.u32.u64 %0, t; }" : "=r"(a) : "l"(p));
    return a;
}

// dummy kernel: keeps ncu capture index landing on a hot kernel
__global__ void align_kernel() {}

// ============================================================================
// Transpose kernel: coalesced read of wcv, scatter to d_wt[g][c][o].
// ============================================================================
__global__ void transpose_kernel(const float* __restrict__ wcv)
{
    int base = blockIdx.x * 1024;
    int tid = threadIdx.x;
    #pragma unroll
    for (int k = 0; k < 4; k++) {
        int idx = base + k*256 + tid;          // idx = o*192 + g*64 + c
        int o = idx / 192, r = idx - o*192;
        int g = r >> 6, c = r & 63;
        d_wt[g*4096 + c*64 + o] = wcv[idx];
    }
}

// ============================================================================
// Kernel A: 4-parity-class MLP + per-class mixed matrices (1 block, s2).
// ============================================================================
__global__ void param_kernel(const float* __restrict__ wce, const float* __restrict__ wee,
                             const float* __restrict__ w1,  const float* __restrict__ b1,
                             const float* __restrict__ w2,  const float* __restrict__ b2,
                             const float* __restrict__ wr,  const float* __restrict__ br,
                             const float* __restrict__ wo,  const float* __restrict__ bo,
                             const int* __restrict__ scale_p, const int* __restrict__ scale2_p)
{
    int tid = threadIdx.x;   // 256
    __shared__ float s_emb1[4][64];
    __shared__ float s_emb [4][64];
    __shared__ float s_rout[4][4];
    int cls = tid >> 6, o = tid & 63;
    float sc  = (float)(*scale_p);
    float sc2 = (float)(*scale2_p);

    int ip = cls >> 1, jp = cls & 1;
    float ihv = (ip + 0.5f) / sc;
    float ch  = ihv - floorf(ihv + 0.001f) - 0.5f;
    float iwv = (jp + 0.5f) / sc2;
    float cw  = iwv - floorf(iwv + 0.001f) - 0.5f;
    float i0 = 1.0f / sc2, i1 = 1.0f / sc;

    float4 w1v = __ldg((const float4*)(w1 + o*4));
    float z = w1v.x*i0 + w1v.y*i1 + w1v.z*ch + w1v.w*cw + b1[o];
    s_emb1[cls][o] = fmaxf(z, 0.0f);
    __syncthreads();

    float z2 = b2[o];
    const float4* w2v = (const float4*)(w2 + o*64);
    #pragma unroll
    for (int j4 = 0; j4 < 16; j4++) {
        float4 wv = __ldg(&w2v[j4]);
        z2 += wv.x*s_emb1[cls][j4*4+0] + wv.y*s_emb1[cls][j4*4+1]
            + wv.z*s_emb1[cls][j4*4+2] + wv.w*s_emb1[cls][j4*4+3];
    }
    s_emb[cls][o] = fmaxf(z2, 0.0f);
    __syncthreads();

    if (o < 4) {
        float zr = br[o];
        const float4* wrv = (const float4*)(wr + o*64);
        #pragma unroll
        for (int j4 = 0; j4 < 16; j4++) {
            float4 wv = __ldg(&wrv[j4]);
            zr += wv.x*s_emb[cls][j4*4+0] + wv.y*s_emb[cls][j4*4+1]
                + wv.z*s_emb[cls][j4*4+2] + wv.w*s_emb[cls][j4*4+3];
        }
        s_rout[cls][o] = 1.0f / (1.0f + expf(-zr));
    } else if (o < 6) {
        int d = o - 4;
        float zo = bo[d];
        const float4* wov = (const float4*)(wo + d*64);
        #pragma unroll
        for (int j4 = 0; j4 < 16; j4++) {
            float4 wv = __ldg(&wov[j4]);
            zo += wv.x*s_emb[cls][j4*4+0] + wv.y*s_emb[cls][j4*4+1]
                + wv.z*s_emb[cls][j4*4+2] + wv.w*s_emb[cls][j4*4+3];
        }
        d_offs[cls*2 + d] = zo;
    }
    __syncthreads();

    for (int idx = tid; idx < 4*512; idx += 256) {
        int cc = idx >> 9, r = idx & 511, c = r & 63, k = r >> 6;
        float r0 = s_rout[cc][0], r1 = s_rout[cc][1], r2 = s_rout[cc][2], r3 = s_rout[cc][3];
        float vc = r0*wce[0*512 + k*64 + c] + r1*wce[1*512 + k*64 + c]
                 + r2*wce[2*512 + k*64 + c] + r3*wce[3*512 + k*64 + c];
        d_wcmix[cc*512 + c*8 + k] = make_float2(vc, vc);
        float ve = r0*wee[0*512 + c*8 + k] + r1*wee[1*512 + c*8 + k]
                 + r2*wee[2*512 + c*8 + k] + r3*wee[3*512 + c*8 + k];
        d_wemix[cc*512 + c*8 + k] = make_float2(ve, ve);
    }
}

// ============================================================================
// Kernel B: fused Sobel + 1x1 conv (192->64), 16x8 tile, 128 threads,
// out-channel halves, 2 pixels/thread. Double-buffered cp.async staging:
// chunk k+1 loads overlap chunk k compute.
// ============================================================================
__global__ __launch_bounds__(128, 4) void feat_kernel(const float* __restrict__ x,
                                                      const float* __restrict__ bcv)
{
    __shared__ float s_tile[2][16][180];   // 23040 B
    __shared__ float s_w[2][16][192];      // 24576 B
    int tid = threadIdx.x;
    int slot = tid & 63;
    int half = tid >> 6;
    int obase = half * 32;
    int r0 = slot >> 4;
    int cx = slot & 15;
    int bx = blockIdx.x * 16, by = blockIdx.y * 8;
    int batch = blockIdx.z;
    const float* xb = x + batch * (C*NPIX);

    unsigned int st_base = smem_u32(&s_tile[0][0][0]);
    unsigned int sw_base = smem_u32(&s_w[0][0][0]);

    ull acc[32];
    #pragma unroll
    for (int i = 0; i < 32; i++) acc[i] = 0ULL;

    // ---- prefetch helper ----
    auto prefetch = [&](int chunk, int buf) {
        int ccb = chunk * 16;
        for (int e = tid; e < 2880; e += 128) {
            int c8 = e / 180, p = e - c8*180;
            int py = p / 18, px = p - py*18;
            int gy = by + py - 1, gx = bx + px - 1;
            bool ok = (gy >= 0 && gy < H && gx >= 0 && gx < W);
            const float* src = xb + (ccb + c8)*NPIX + gy*W + gx;
            unsigned int dst = st_base + (unsigned int)(buf*2880 + e)*4u;
            int szr = ok ? 4 : 0;
            asm volatile("cp.async.ca.shared.global [%0], [%1], 4, %2;"
                         :: "r"(dst), "l"(src), "r"(szr) : "memory");
        }
        for (int e = tid; e < 3072; e += 128) {
            int c8 = e / 192, r = e - c8*192;
            int g = r >> 6, oo = r & 63;
            const float* src = &d_wt[g*4096 + (ccb + c8)*64 + oo];
            unsigned int dst = sw_base + (unsigned int)(buf*3072 + e)*4u;
            asm volatile("cp.async.ca.shared.global [%0], [%1], 4;"
                         :: "r"(dst), "l"(src) : "memory");
        }
        asm volatile("cp.async.commit_group;" ::: "memory");
    };

    prefetch(0, 0);

    for (int k = 0; k < 4; k++) {
        if (k < 3) {
            prefetch(k + 1, (k + 1) & 1);
            asm volatile("cp.async.wait_group 1;" ::: "memory");
        } else {
            asm volatile("cp.async.wait_group 0;" ::: "memory");
        }
        __syncthreads();
        int buf = k & 1;

        #pragma unroll 1
        for (int c8 = 0; c8 < 16; c8++) {
            const float* t = &s_tile[buf][c8][r0*18 + cx];
            float a00=t[0],  a01=t[1],  a02=t[2];
            float a10=t[18], a11=t[19], a12=t[20];
            float a20=t[36], a21=t[37], a22=t[38];
            const float* u = t + 72;
            float b00=u[0],  b01=u[1],  b02=u[2];
            float b10=u[18], b11=u[19], b12=u[20];
            float b20=u[36], b21=u[37], b22=u[38];

            float va  = a11;
            float gxa = (a02 - a00) + 2.0f*(a12 - a10) + (a22 - a20);
            float gya = (a20 - a00) + 2.0f*(a21 - a01) + (a22 - a02);
            float vb  = b11;
            float gxb = (b02 - b00) + 2.0f*(b12 - b10) + (b22 - b20);
            float gyb = (b20 - b00) + 2.0f*(b21 - b01) + (b22 - b02);

            ull VA = pk2(va, va),  GXA = pk2(gxa, gxa), GYA = pk2(gya, gya);
            ull VB = pk2(vb, vb),  GXB = pk2(gxb, gxb), GYB = pk2(gyb, gyb);

            const ulonglong2* w0p = (const ulonglong2*)&s_w[buf][c8][  0 + obase];
            const ulonglong2* w1p = (const ulonglong2*)&s_w[buf][c8][ 64 + obase];
            const ulonglong2* w2p = (const ulonglong2*)&s_w[buf][c8][128 + obase];
            #pragma unroll
            for (int wg = 0; wg < 8; wg++) {
                ulonglong2 w0 = w0p[wg], w1 = w1p[wg], w2 = w2p[wg];
                acc[wg*2+0]    = fma2(w0.x, VA,  acc[wg*2+0]);
                acc[wg*2+1]    = fma2(w0.y, VA,  acc[wg*2+1]);
                acc[16+wg*2+0] = fma2(w0.x, VB,  acc[16+wg*2+0]);
                acc[16+wg*2+1] = fma2(w0.y, VB,  acc[16+wg*2+1]);
                acc[wg*2+0]    = fma2(w1.x, GXA, acc[wg*2+0]);
                acc[wg*2+1]    = fma2(w1.y, GXA, acc[wg*2+1]);
                acc[16+wg*2+0] = fma2(w1.x, GXB, acc[16+wg*2+0]);
                acc[16+wg*2+1] = fma2(w1.y, GXB, acc[16+wg*2+1]);
                acc[wg*2+0]    = fma2(w2.x, GYA, acc[wg*2+0]);
                acc[wg*2+1]    = fma2(w2.y, GYA, acc[wg*2+1]);
                acc[16+wg*2+0] = fma2(w2.x, GYB, acc[16+wg*2+0]);
                acc[16+wg*2+1] = fma2(w2.y, GYB, acc[16+wg*2+1]);
            }
        }
        __syncthreads();
    }

    int pixA = (by + r0)*W + (bx + cx);
    int pixB = pixA + 4*W;
    float* fout = (float*)d_feat2;
    #pragma unroll
    for (int wg = 0; wg < 8; wg++) {
        #pragma unroll
        for (int hh = 0; hh < 2; hh++) {
            int o0 = obase + wg*4 + hh*2;
            float bi0 = __ldg(&bcv[o0]), bi1 = __ldg(&bcv[o0+1]);
            float2 ra = upk(acc[wg*2 + hh]);
            fout[( o0   *NPIX + pixA)*2 + batch] = ra.x + bi0;
            fout[((o0+1)*NPIX + pixA)*2 + batch] = ra.y + bi1;
            float2 rb = upk(acc[16 + wg*2 + hh]);
            fout[( o0   *NPIX + pixB)*2 + batch] = rb.x + bi0;
            fout[((o0+1)*NPIX + pixB)*2 + batch] = rb.y + bi1;
        }
    }
}

// ============================================================================
// Kernel C: bilinear sample + per-class compress/expand + residual.
// 32x4 tile, 256 threads; warp = (class, channel-half). (R10 version, untouched)
// ============================================================================
__global__ __launch_bounds__(256, 2) void up_kernel(float* __restrict__ out)
{
    extern __shared__ char smem_raw[];
    float2* s_wc  = (float2*)smem_raw;          // 16KB  (reused as s_mid after pass1)
    float2* s_we  = s_wc + 2048;                // 16KB
    ull*    s_fea = (ull*)(s_we + 2048);        // 64KB: [c][pslot]
    ull*    s_mid = (ull*)smem_raw;             // overlay
    __shared__ float s_o[8];

    int tid = threadIdx.x;
    for (int e = tid; e < 2048; e += 256) { s_wc[e] = d_wcmix[e]; s_we[e] = d_wemix[e]; }
    if (tid < 8) s_o[tid] = d_offs[tid];
    __syncthreads();

    int warp = tid >> 5, lane = tid & 31;
    int cls  = warp & 3;
    int half = warp >> 2;
    int pslot = cls*32 + lane;
    int i = blockIdx.y*4  + ((lane >> 4) << 1) + (cls >> 1);
    int j = blockIdx.x*32 + ((lane & 15) << 1) + (cls & 1);
    float offx = s_o[cls*2+0], offy = s_o[cls*2+1];

    float gy = ((i + 0.5f)*0.5f - 0.5f)*(2.0f/(H-1)) - 1.0f + offy*(2.0f/(H-1));
    float iyf = ((gy + 1.0f)*H - 1.0f)*0.5f;
    float y0f = floorf(iyf);
    float fy = iyf - y0f;
    int y0 = (int)y0f;
    float wy0 = 1.0f - fy, wy1 = fy;
    bool vy0 = (y0   >= 0) && (y0   < H);
    bool vy1 = (y0+1 >= 0) && (y0+1 < H);
    int cy0 = min(max(y0,   0), H-1);
    int cy1 = min(max(y0+1, 0), H-1);

    float gx = ((j + 0.5f)*0.5f - 0.5f)*(2.0f/(W-1)) - 1.0f + offx*(2.0f/(W-1));
    float ixf = ((gx + 1.0f)*W - 1.0f)*0.5f;
    float x0f = floorf(ixf);
    float fx = ixf - x0f;
    int x0 = (int)x0f;
    float wx0 = 1.0f - fx, wx1 = fx;
    bool vx0 = (x0   >= 0) && (x0   < W);
    bool vx1 = (x0+1 >= 0) && (x0+1 < W);
    float w00 = (vx0 && vy0) ? wx0*wy0 : 0.0f;
    float w01 = (vx1 && vy0) ? wx1*wy0 : 0.0f;
    float w10 = (vx0 && vy1) ? wx0*wy1 : 0.0f;
    float w11 = (vx1 && vy1) ? wx1*wy1 : 0.0f;
    int cx0 = min(max(x0,   0), W-1), cx1 = min(max(x0+1, 0), W-1);
    ull W00 = pk2(w00,w00), W01 = pk2(w01,w01), W10 = pk2(w10,w10), W11 = pk2(w11,w11);

    const ull* fb  = (const ull*)d_feat2 + (size_t)half*32*NPIX;
    const ull* P00 = fb + cy0*W + cx0;
    const ull* P01 = fb + cy0*W + cx1;
    const ull* P10 = fb + cy1*W + cx0;
    const ull* P11 = fb + cy1*W + cx1;

    const ulonglong2* wcp = (const ulonglong2*)(s_wc + cls*512) + half*32*4;
    ull* fp = s_fea + (size_t)half*32*128 + pslot;
    ull midp[8] = {0,0,0,0,0,0,0,0};
    #pragma unroll 4
    for (int cc = 0; cc < 32; cc++) {
        ull v =  mul2(W00, P00[cc*NPIX]);
        v = fma2(W01, P01[cc*NPIX], v);
        v = fma2(W10, P10[cc*NPIX], v);
        v = fma2(W11, P11[cc*NPIX], v);
        fp[cc*128] = v;
        #pragma unroll
        for (int kk = 0; kk < 4; kk++) {
            ulonglong2 w = wcp[cc*4 + kk];
            midp[kk*2  ] = fma2(w.x, v, midp[kk*2  ]);
            midp[kk*2+1] = fma2(w.y, v, midp[kk*2+1]);
        }
    }

    __syncthreads();
    #pragma unroll
    for (int k = 0; k < 8; k++)
        s_mid[(half*8 + k)*128 + pslot] = midp[k];
    __syncthreads();
    ull mid[8];
    #pragma unroll
    for (int k = 0; k < 8; k++) {
        float2 a = upk(midp[k]);
        float2 b = upk(s_mid[((1-half)*8 + k)*128 + pslot]);
        mid[k] = pk2(a.x + b.x, a.y + b.y);
    }

    const ulonglong2* wep = (const ulonglong2*)(s_we + cls*512) + half*32*4;
    float* o0 = out +          i*SW + j;
    float* o1 = out + C*NOUT + i*SW + j;
    #pragma unroll 4
    for (int cc = 0; cc < 32; cc++) {
        ull v = fp[cc*128];
        #pragma unroll
        for (int kk = 0; kk < 4; kk++) {
            ulonglong2 w = wep[cc*4 + kk];
            v = fma2(w.x, mid[kk*2  ], v);
            v = fma2(w.y, mid[kk*2+1], v);
        }
        float2 rr = upk(v);
        int cg = half*32 + cc;
        __stwt(&o0[(size_t)cg*NOUT], rr.x);
        __stwt(&o1[(size_t)cg*NOUT], rr.y);
    }
}

// ============================================================================
extern "C" void kernel_launch(void* const* d_in, const int* in_sizes, int n_in,
                              void* d_out, int out_size)
{
    const float* x   = (const float*)d_in[0];
    const float* wce = (const float*)d_in[1];
    const float* wee = (const float*)d_in[2];
    const float* w1  = (const float*)d_in[3];
    const float* b1  = (const float*)d_in[4];
    const float* w2  = (const float*)d_in[5];
    const float* b2  = (const float*)d_in[6];
    const float* wr  = (const float*)d_in[7];
    const float* br  = (const float*)d_in[8];
    const float* wo  = (const float*)d_in[9];
    const float* bo  = (const float*)d_in[10];
    const float* wcv = (const float*)d_in[11];
    const float* bcv = (const float*)d_in[12];
    const int* scale_p  = (const int*)d_in[13];
    const int* scale2_p = (const int*)d_in[14];
    float* out = (float*)d_out;

    static cudaStream_t s2 = nullptr;
    static cudaEvent_t evFork = nullptr, evParam = nullptr;
    static int init_done = 0;
    if (!init_done) {
        cudaFuncSetAttribute(up_kernel, cudaFuncAttributeMaxDynamicSharedMemorySize, 98304);
        cudaStreamCreateWithFlags(&s2, cudaStreamNonBlocking);
        cudaEventCreateWithFlags(&evFork,  cudaEventDisableTiming);
        cudaEventCreateWithFlags(&evParam, cudaEventDisableTiming);
        init_done = 1;
    }

    align_kernel<<<1, 32>>>();   // profiling index alignment

    // fork param onto s2 (only up depends on it)
    cudaEventRecord(evFork, 0);
    cudaStreamWaitEvent(s2, evFork, 0);
    param_kernel<<<1, 256, 0, s2>>>(wce, wee, w1, b1, w2, b2, wr, br, wo, bo, scale_p, scale2_p);
    cudaEventRecord(evParam, s2);

    // stream 0: transpose + feat
    transpose_kernel<<<12, 256>>>(wcv);
    dim3 gb(W/16, H/8, B);
    feat_kernel<<<gb, 128>>>(x, bcv);

    // join param, then up
    cudaStreamWaitEvent(0, evParam, 0);
    dim3 gc(SW/32, SH/4);
    up_kernel<<<gc, 256, 98304>>>(out);
}

// round 16
// speedup vs baseline: 1.4851x; 1.0207x over previous
#include <cuda_runtime.h>
#include <stdint.h>
#include <math.h>

#define B    2
#define C    64
#define H    192
#define W    192
#define SH   384
#define SW   384
#define NPIX (H*W)     // 36864
#define NOUT (SH*SW)   // 147456

typedef unsigned long long ull;

// ---------------- device scratch ----------------
__device__ float2 d_feat2[C*NPIX];     // feat channel-major: [c][pix] -> (b0,b1)
__device__ float  d_wt[3*C*C];         // conv weights transposed: [g][c][o]
__device__ float2 d_wcmix[4*C*8];      // per-class mixed compress, dup-packed [cls][c][k]
__device__ float2 d_wemix[4*C*8];      // per-class mixed expand,   dup-packed [cls][c][k]
__device__ float  d_offs[8];           // per-class offsets

// ---------------- packed f32x2 helpers ----------------
__device__ __forceinline__ ull fma2(ull a, ull b, ull c){
    ull d; asm("fma.rn.f32x2 %0, %1, %2, %3;" : "=l"(d) : "l"(a), "l"(b), "l"(c)); return d;
}
__device__ __forceinline__ ull mul2(ull a, ull b){
    ull d; asm("mul.rn.f32x2 %0, %1, %2;" : "=l"(d) : "l"(a), "l"(b)); return d;
}
__device__ __forceinline__ ull pk2(float x, float y){
    ull u; asm("mov.b64 %0, {%1, %2};" : "=l"(u) : "f"(x), "f"(y)); return u;
}
__device__ __forceinline__ float2 upk(ull u){
    float2 v; asm("mov.b64 {%0, %1}, %2;" : "=f"(v.x), "=f"(v.y) : "l"(u)); return v;
}
__device__ __forceinline__ unsigned int smem_u32(const void* p){
    unsigned int a;
    asm("{ .reg .u64 t; cvta.to.shared.u64 t, %1; cvt.u32.u64 %0, t; }" : "=r"(a) : "l"(p));
    return a;
}

// dummy kernel: keeps ncu capture index landing on a hot kernel
__global__ void align_kernel() {}

// ============================================================================
// Transpose kernel: coalesced read of wcv, scatter to d_wt[g][c][o].
// ============================================================================
__global__ void transpose_kernel(const float* __restrict__ wcv)
{
    int base = blockIdx.x * 1024;
    int tid = threadIdx.x;
    #pragma unroll
    for (int k = 0; k < 4; k++) {
        int idx = base + k*256 + tid;          // idx = o*192 + g*64 + c
        int o = idx / 192, r = idx - o*192;
        int g = r >> 6, c = r & 63;
        d_wt[g*4096 + c*64 + o] = wcv[idx];
    }
}

// ============================================================================
// Kernel A: 4-parity-class MLP + per-class mixed matrices (1 block, s2).
// ============================================================================
__global__ void param_kernel(const float* __restrict__ wce, const float* __restrict__ wee,
                             const float* __restrict__ w1,  const float* __restrict__ b1,
                             const float* __restrict__ w2,  const float* __restrict__ b2,
                             const float* __restrict__ wr,  const float* __restrict__ br,
                             const float* __restrict__ wo,  const float* __restrict__ bo,
                             const int* __restrict__ scale_p, const int* __restrict__ scale2_p)
{
    int tid = threadIdx.x;   // 256
    __shared__ float s_emb1[4][64];
    __shared__ float s_emb [4][64];
    __shared__ float s_rout[4][4];
    int cls = tid >> 6, o = tid & 63;
    float sc  = (float)(*scale_p);
    float sc2 = (float)(*scale2_p);

    int ip = cls >> 1, jp = cls & 1;
    float ihv = (ip + 0.5f) / sc;
    float ch  = ihv - floorf(ihv + 0.001f) - 0.5f;
    float iwv = (jp + 0.5f) / sc2;
    float cw  = iwv - floorf(iwv + 0.001f) - 0.5f;
    float i0 = 1.0f / sc2, i1 = 1.0f / sc;

    float4 w1v = __ldg((const float4*)(w1 + o*4));
    float z = w1v.x*i0 + w1v.y*i1 + w1v.z*ch + w1v.w*cw + b1[o];
    s_emb1[cls][o] = fmaxf(z, 0.0f);
    __syncthreads();

    float z2 = b2[o];
    const float4* w2v = (const float4*)(w2 + o*64);
    #pragma unroll
    for (int j4 = 0; j4 < 16; j4++) {
        float4 wv = __ldg(&w2v[j4]);
        z2 += wv.x*s_emb1[cls][j4*4+0] + wv.y*s_emb1[cls][j4*4+1]
            + wv.z*s_emb1[cls][j4*4+2] + wv.w*s_emb1[cls][j4*4+3];
    }
    s_emb[cls][o] = fmaxf(z2, 0.0f);
    __syncthreads();

    if (o < 4) {
        float zr = br[o];
        const float4* wrv = (const float4*)(wr + o*64);
        #pragma unroll
        for (int j4 = 0; j4 < 16; j4++) {
            float4 wv = __ldg(&wrv[j4]);
            zr += wv.x*s_emb[cls][j4*4+0] + wv.y*s_emb[cls][j4*4+1]
                + wv.z*s_emb[cls][j4*4+2] + wv.w*s_emb[cls][j4*4+3];
        }
        s_rout[cls][o] = 1.0f / (1.0f + expf(-zr));
    } else if (o < 6) {
        int d = o - 4;
        float zo = bo[d];
        const float4* wov = (const float4*)(wo + d*64);
        #pragma unroll
        for (int j4 = 0; j4 < 16; j4++) {
            float4 wv = __ldg(&wov[j4]);
            zo += wv.x*s_emb[cls][j4*4+0] + wv.y*s_emb[cls][j4*4+1]
                + wv.z*s_emb[cls][j4*4+2] + wv.w*s_emb[cls][j4*4+3];
        }
        d_offs[cls*2 + d] = zo;
    }
    __syncthreads();

    for (int idx = tid; idx < 4*512; idx += 256) {
        int cc = idx >> 9, r = idx & 511, c = r & 63, k = r >> 6;
        float r0 = s_rout[cc][0], r1 = s_rout[cc][1], r2 = s_rout[cc][2], r3 = s_rout[cc][3];
        float vc = r0*wce[0*512 + k*64 + c] + r1*wce[1*512 + k*64 + c]
                 + r2*wce[2*512 + k*64 + c] + r3*wce[3*512 + k*64 + c];
        d_wcmix[cc*512 + c*8 + k] = make_float2(vc, vc);
        float ve = r0*wee[0*512 + c*8 + k] + r1*wee[1*512 + c*8 + k]
                 + r2*wee[2*512 + c*8 + k] + r3*wee[3*512 + c*8 + k];
        d_wemix[cc*512 + c*8 + k] = make_float2(ve, ve);
    }
}

// ============================================================================
// Kernel B: fused Sobel + 1x1 conv (192->64), 16x8 tile, 128 threads,
// out-channel halves, 2 pixels/thread. Double-buffered 16B cp.async staging.
// Tile rows staged as 24-float 16B-aligned windows [bx-4, bx+20); halo lives
// at indices 3..20; boundary float4s are fully-valid or fully-zfill.
// ============================================================================
#define TILE_F  3840   // 16 c8 * 10 rows * 24 floats (per buffer)
#define WREG_F  3072   // 16 c8 * 192 floats (per buffer)
__global__ __launch_bounds__(128, 4) void feat_kernel(const float* __restrict__ x,
                                                      const float* __restrict__ bcv)
{
    extern __shared__ float fsm[];               // [2*TILE_F tile | 2*WREG_F weights]
    float* st = fsm;                             // tile, row stride 24
    float* sw = fsm + 2*TILE_F;                  // weights
    int tid = threadIdx.x;
    int slot = tid & 63;
    int half = tid >> 6;
    int obase = half * 32;
    int r0 = slot >> 4;
    int cx = slot & 15;
    int bx = blockIdx.x * 16, by = blockIdx.y * 8;
    int batch = blockIdx.z;
    const float* xb = x + batch * (C*NPIX);

    unsigned int st_base = smem_u32(st);
    unsigned int sw_base = smem_u32(sw);

    ull acc[32];
    #pragma unroll
    for (int i = 0; i < 32; i++) acc[i] = 0ULL;

    auto prefetch = [&](int chunk, int buf) {
        int ccb = chunk * 16;
        // tile: 960 float4 per chunk
        for (int e = tid; e < 960; e += 128) {
            int c8 = e / 60, rem = e - c8*60;
            int py = rem / 6, q = rem - py*6;
            int gy = by + py - 1;
            int gxs = bx - 4 + q*4;
            bool ok = (gy >= 0) && (gy < H) && (gxs >= 0) && (gxs + 3 < W);
            const float* src = xb + (ccb + c8)*NPIX + gy*W + gxs;
            unsigned int dst = st_base + (unsigned int)(buf*TILE_F + c8*240 + py*24 + q*4)*4u;
            int szr = ok ? 16 : 0;
            asm volatile("cp.async.cg.shared.global [%0], [%1], 16, %2;"
                         :: "r"(dst), "l"(src), "r"(szr) : "memory");
        }
        // weights: 768 float4 per chunk
        for (int e = tid; e < 768; e += 128) {
            int c8 = e / 48, rem = e - c8*48;
            int g = rem >> 4, o4 = rem & 15;
            const float* src = &d_wt[g*4096 + (ccb + c8)*64 + o4*4];
            unsigned int dst = sw_base + (unsigned int)(buf*WREG_F + c8*192 + g*64 + o4*4)*4u;
            asm volatile("cp.async.cg.shared.global [%0], [%1], 16;"
                         :: "r"(dst), "l"(src) : "memory");
        }
        asm volatile("cp.async.commit_group;" ::: "memory");
    };

    prefetch(0, 0);

    for (int k = 0; k < 4; k++) {
        if (k < 3) {
            prefetch(k + 1, (k + 1) & 1);
            asm volatile("cp.async.wait_group 1;" ::: "memory");
        } else {
            asm volatile("cp.async.wait_group 0;" ::: "memory");
        }
        __syncthreads();
        int buf = k & 1;
        const float* tb = st + buf*TILE_F;
        const float* wb = sw + buf*WREG_F;

        #pragma unroll 1
        for (int c8 = 0; c8 < 16; c8++) {
            const float* t = tb + c8*240 + r0*24 + cx + 3;
            float a00=t[0],  a01=t[1],  a02=t[2];
            float a10=t[24], a11=t[25], a12=t[26];
            float a20=t[48], a21=t[49], a22=t[50];
            const float* u = t + 96;     // pixel1: row r0+4
            float b00=u[0],  b01=u[1],  b02=u[2];
            float b10=u[24], b11=u[25], b12=u[26];
            float b20=u[48], b21=u[49], b22=u[50];

            float va  = a11;
            float gxa = (a02 - a00) + 2.0f*(a12 - a10) + (a22 - a20);
            float gya = (a20 - a00) + 2.0f*(a21 - a01) + (a22 - a02);
            float vb  = b11;
            float gxb = (b02 - b00) + 2.0f*(b12 - b10) + (b22 - b20);
            float gyb = (b20 - b00) + 2.0f*(b21 - b01) + (b22 - b02);

            ull VA = pk2(va, va),  GXA = pk2(gxa, gxa), GYA = pk2(gya, gya);
            ull VB = pk2(vb, vb),  GXB = pk2(gxb, gxb), GYB = pk2(gyb, gyb);

            const ulonglong2* w0p = (const ulonglong2*)(wb + c8*192 +   0 + obase);
            const ulonglong2* w1p = (const ulonglong2*)(wb + c8*192 +  64 + obase);
            const ulonglong2* w2p = (const ulonglong2*)(wb + c8*192 + 128 + obase);
            #pragma unroll
            for (int wg = 0; wg < 8; wg++) {
                ulonglong2 w0 = w0p[wg], w1 = w1p[wg], w2 = w2p[wg];
                acc[wg*2+0]    = fma2(w0.x, VA,  acc[wg*2+0]);
                acc[wg*2+1]    = fma2(w0.y, VA,  acc[wg*2+1]);
                acc[16+wg*2+0] = fma2(w0.x, VB,  acc[16+wg*2+0]);
                acc[16+wg*2+1] = fma2(w0.y, VB,  acc[16+wg*2+1]);
                acc[wg*2+0]    = fma2(w1.x, GXA, acc[wg*2+0]);
                acc[wg*2+1]    = fma2(w1.y, GXA, acc[wg*2+1]);
                acc[16+wg*2+0] = fma2(w1.x, GXB, acc[16+wg*2+0]);
                acc[16+wg*2+1] = fma2(w1.y, GXB, acc[16+wg*2+1]);
                acc[wg*2+0]    = fma2(w2.x, GYA, acc[wg*2+0]);
                acc[wg*2+1]    = fma2(w2.y, GYA, acc[wg*2+1]);
                acc[16+wg*2+0] = fma2(w2.x, GYB, acc[16+wg*2+0]);
                acc[16+wg*2+1] = fma2(w2.y, GYB, acc[16+wg*2+1]);
            }
        }
        __syncthreads();
    }

    int pixA = (by + r0)*W + (bx + cx);
    int pixB = pixA + 4*W;
    float* fout = (float*)d_feat2;
    #pragma unroll
    for (int wg = 0; wg < 8; wg++) {
        #pragma unroll
        for (int hh = 0; hh < 2; hh++) {
            int o0 = obase + wg*4 + hh*2;
            float bi0 = __ldg(&bcv[o0]), bi1 = __ldg(&bcv[o0+1]);
            float2 ra = upk(acc[wg*2 + hh]);
            fout[( o0   *NPIX + pixA)*2 + batch] = ra.x + bi0;
            fout[((o0+1)*NPIX + pixA)*2 + batch] = ra.y + bi1;
            float2 rb = upk(acc[16 + wg*2 + hh]);
            fout[( o0   *NPIX + pixB)*2 + batch] = rb.x + bi0;
            fout[((o0+1)*NPIX + pixB)*2 + batch] = rb.y + bi1;
        }
    }
}
#define FEAT_SMEM ((2*TILE_F + 2*WREG_F)*4)   // 55296 bytes

// ============================================================================
// Kernel C: bilinear sample + per-class compress/expand + residual.
// 32x4 tile, 256 threads; warp = (class, channel-half). (untouched)
// ============================================================================
__global__ __launch_bounds__(256, 2) void up_kernel(float* __restrict__ out)
{
    extern __shared__ char smem_raw[];
    float2* s_wc  = (float2*)smem_raw;          // 16KB  (reused as s_mid after pass1)
    float2* s_we  = s_wc + 2048;                // 16KB
    ull*    s_fea = (ull*)(s_we + 2048);        // 64KB: [c][pslot]
    ull*    s_mid = (ull*)smem_raw;             // overlay
    __shared__ float s_o[8];

    int tid = threadIdx.x;
    for (int e = tid; e < 2048; e += 256) { s_wc[e] = d_wcmix[e]; s_we[e] = d_wemix[e]; }
    if (tid < 8) s_o[tid] = d_offs[tid];
    __syncthreads();

    int warp = tid >> 5, lane = tid & 31;
    int cls  = warp & 3;
    int half = warp >> 2;
    int pslot = cls*32 + lane;
    int i = blockIdx.y*4  + ((lane >> 4) << 1) + (cls >> 1);
    int j = blockIdx.x*32 + ((lane & 15) << 1) + (cls & 1);
    float offx = s_o[cls*2+0], offy = s_o[cls*2+1];

    float gy = ((i + 0.5f)*0.5f - 0.5f)*(2.0f/(H-1)) - 1.0f + offy*(2.0f/(H-1));
    float iyf = ((gy + 1.0f)*H - 1.0f)*0.5f;
    float y0f = floorf(iyf);
    float fy = iyf - y0f;
    int y0 = (int)y0f;
    float wy0 = 1.0f - fy, wy1 = fy;
    bool vy0 = (y0   >= 0) && (y0   < H);
    bool vy1 = (y0+1 >= 0) && (y0+1 < H);
    int cy0 = min(max(y0,   0), H-1);
    int cy1 = min(max(y0+1, 0), H-1);

    float gx = ((j + 0.5f)*0.5f - 0.5f)*(2.0f/(W-1)) - 1.0f + offx*(2.0f/(W-1));
    float ixf = ((gx + 1.0f)*W - 1.0f)*0.5f;
    float x0f = floorf(ixf);
    float fx = ixf - x0f;
    int x0 = (int)x0f;
    float wx0 = 1.0f - fx, wx1 = fx;
    bool vx0 = (x0   >= 0) && (x0   < W);
    bool vx1 = (x0+1 >= 0) && (x0+1 < W);
    float w00 = (vx0 && vy0) ? wx0*wy0 : 0.0f;
    float w01 = (vx1 && vy0) ? wx1*wy0 : 0.0f;
    float w10 = (vx0 && vy1) ? wx0*wy1 : 0.0f;
    float w11 = (vx1 && vy1) ? wx1*wy1 : 0.0f;
    int cx0 = min(max(x0,   0), W-1), cx1 = min(max(x0+1, 0), W-1);
    ull W00 = pk2(w00,w00), W01 = pk2(w01,w01), W10 = pk2(w10,w10), W11 = pk2(w11,w11);

    const ull* fb  = (const ull*)d_feat2 + (size_t)half*32*NPIX;
    const ull* P00 = fb + cy0*W + cx0;
    const ull* P01 = fb + cy0*W + cx1;
    const ull* P10 = fb + cy1*W + cx0;
    const ull* P11 = fb + cy1*W + cx1;

    const ulonglong2* wcp = (const ulonglong2*)(s_wc + cls*512) + half*32*4;
    ull* fp = s_fea + (size_t)half*32*128 + pslot;
    ull midp[8] = {0,0,0,0,0,0,0,0};
    #pragma unroll 4
    for (int cc = 0; cc < 32; cc++) {
        ull v =  mul2(W00, P00[cc*NPIX]);
        v = fma2(W01, P01[cc*NPIX], v);
        v = fma2(W10, P10[cc*NPIX], v);
        v = fma2(W11, P11[cc*NPIX], v);
        fp[cc*128] = v;
        #pragma unroll
        for (int kk = 0; kk < 4; kk++) {
            ulonglong2 w = wcp[cc*4 + kk];
            midp[kk*2  ] = fma2(w.x, v, midp[kk*2  ]);
            midp[kk*2+1] = fma2(w.y, v, midp[kk*2+1]);
        }
    }

    __syncthreads();
    #pragma unroll
    for (int k = 0; k < 8; k++)
        s_mid[(half*8 + k)*128 + pslot] = midp[k];
    __syncthreads();
    ull mid[8];
    #pragma unroll
    for (int k = 0; k < 8; k++) {
        float2 a = upk(midp[k]);
        float2 b = upk(s_mid[((1-half)*8 + k)*128 + pslot]);
        mid[k] = pk2(a.x + b.x, a.y + b.y);
    }

    const ulonglong2* wep = (const ulonglong2*)(s_we + cls*512) + half*32*4;
    float* o0 = out +          i*SW + j;
    float* o1 = out + C*NOUT + i*SW + j;
    #pragma unroll 4
    for (int cc = 0; cc < 32; cc++) {
        ull v = fp[cc*128];
        #pragma unroll
        for (int kk = 0; kk < 4; kk++) {
            ulonglong2 w = wep[cc*4 + kk];
            v = fma2(w.x, mid[kk*2  ], v);
            v = fma2(w.y, mid[kk*2+1], v);
        }
        float2 rr = upk(v);
        int cg = half*32 + cc;
        __stwt(&o0[(size_t)cg*NOUT], rr.x);
        __stwt(&o1[(size_t)cg*NOUT], rr.y);
    }
}

// ============================================================================
extern "C" void kernel_launch(void* const* d_in, const int* in_sizes, int n_in,
                              void* d_out, int out_size)
{
    const float* x   = (const float*)d_in[0];
    const float* wce = (const float*)d_in[1];
    const float* wee = (const float*)d_in[2];
    const float* w1  = (const float*)d_in[3];
    const float* b1  = (const float*)d_in[4];
    const float* w2  = (const float*)d_in[5];
    const float* b2  = (const float*)d_in[6];
    const float* wr  = (const float*)d_in[7];
    const float* br  = (const float*)d_in[8];
    const float* wo  = (const float*)d_in[9];
    const float* bo  = (const float*)d_in[10];
    const float* wcv = (const float*)d_in[11];
    const float* bcv = (const float*)d_in[12];
    const int* scale_p  = (const int*)d_in[13];
    const int* scale2_p = (const int*)d_in[14];
    float* out = (float*)d_out;

    static cudaStream_t s2 = nullptr;
    static cudaEvent_t evFork = nullptr, evParam = nullptr;
    static int init_done = 0;
    if (!init_done) {
        cudaFuncSetAttribute(up_kernel, cudaFuncAttributeMaxDynamicSharedMemorySize, 98304);
        cudaFuncSetAttribute(feat_kernel, cudaFuncAttributeMaxDynamicSharedMemorySize, FEAT_SMEM);
        cudaStreamCreateWithFlags(&s2, cudaStreamNonBlocking);
        cudaEventCreateWithFlags(&evFork,  cudaEventDisableTiming);
        cudaEventCreateWithFlags(&evParam, cudaEventDisableTiming);
        init_done = 1;
    }

    align_kernel<<<1, 32>>>();   // profiling index alignment

    // fork param onto s2 (only up depends on it)
    cudaEventRecord(evFork, 0);
    cudaStreamWaitEvent(s2, evFork, 0);
    param_kernel<<<1, 256, 0, s2>>>(wce, wee, w1, b1, w2, b2, wr, br, wo, bo, scale_p, scale2_p);
    cudaEventRecord(evParam, s2);

    // stream 0: transpose + feat
    transpose_kernel<<<12, 256>>>(wcv);
    dim3 gb(W/16, H/8, B);
    feat_kernel<<<gb, 128, FEAT_SMEM>>>(x, bcv);

    // join param, then up
    cudaStreamWaitEvent(0, evParam, 0);
    dim3 gc(SW/32, SH/4);
    up_kernel<<<gc, 256, 98304>>>(out);
}